// round 10
// baseline (speedup 1.0000x reference)
#include <cuda_runtime.h>

typedef unsigned long long ull;

#define NG 8           // batch groups (32 batches each)
#define NP 16          // column partitions (16 hidden cols each)
#define NBLK (NG*NP)   // 128 CTAs
#define SM_FLOATS 56864
#define SMEM_BYTES (SM_FLOATS*4)

// ---------------- static device scratch (no allocation) ----------------
__device__ float d_pA[NP*256*48];      // W_hh0 packed  [p][k][cp][6]
__device__ float d_pB[NP*256*96];      // W_ih1|W_hh1   [p][k][cp][12]
__device__ float d_pD[NP*256*48];      // Wd_hh packed  [p][k][cp][6]
__device__ float d_h0g[2*NG*256*32];   // double-buffered layer0 h [par][g][col][b]
__device__ float d_h1g[2*NG*256*32];   // layer1 / decoder h
__device__ float d_partg[2*NP*NG*32];  // decoder partial y
__device__ unsigned int d_cnt[NG];     // group barrier counters

// ---------------- prep: reset barriers, pack weights ----------------
__global__ void prep_kernel(const float* __restrict__ Whh0, const float* __restrict__ Wih1,
                            const float* __restrict__ Whh1, const float* __restrict__ Wdhh)
{
    int idx = blockIdx.x*blockDim.x + threadIdx.x;
    int stride = gridDim.x*blockDim.x;
    if (idx < NG) d_cnt[idx] = 0u;
    for (int i = idx; i < NP*256*48; i += stride) {
        int q = i % 6, cp = (i/6) & 7, k = (i/48) & 255, p = i/12288;
        int gate = q >> 1, cl = q & 1;
        int col = p*16 + cp*2 + cl;
        int src = (gate*256 + col)*256 + k;
        d_pA[i] = Whh0[src];
        d_pD[i] = Wdhh[src];
    }
    for (int i = idx; i < NP*256*96; i += stride) {
        int q = i % 12, cp = (i/12) & 7, k = (i/96) & 255, p = i/24576;
        int gate = q >> 2, s = (q >> 1) & 1, cl = q & 1;
        int col = p*16 + cp*2 + cl;
        int src = (gate*256 + col)*256 + k;
        d_pB[i] = s ? Whh1[src] : Wih1[src];
    }
}

// ---------------- helpers ----------------
__device__ __forceinline__ ull splat2(float v){ ull r; asm("mov.b64 %0, {%1,%1};" : "=l"(r) : "f"(v)); return r; }
__device__ __forceinline__ void fma2(ull &d, ull a, ull b){ asm("fma.rn.f32x2 %0, %1, %2, %0;" : "+l"(d) : "l"(a), "l"(b)); }
__device__ __forceinline__ float2 unp(ull v){ float2 f; asm("mov.b64 {%0,%1}, %2;" : "=f"(f.x), "=f"(f.y) : "l"(v)); return f; }
__device__ __forceinline__ float sigf(float v){ return 1.0f/(1.0f + __expf(-v)); }
__device__ __forceinline__ float tanh_(float v){
    float a = fabsf(v), e = __expf(-2.0f*a);
    float t = (1.0f - e)/(1.0f + e);
    return v < 0.0f ? -t : t;
}

// per-group barrier: release(prior stores) -> arrive -> spin -> acquire
__device__ __forceinline__ void gbar(int g, unsigned target){
    __threadfence();
    __syncthreads();
    if (threadIdx.x == 0) {
        atomicAdd(&d_cnt[g], 1u);
        while (*(volatile unsigned*)&d_cnt[g] < target) __nanosleep(32);
        __threadfence();
    }
    __syncthreads();
}

// 48-row packed GEMM (layer0 / decoder): acc over col-pair packed f32x2
__device__ __forceinline__ void gemm48(const float* __restrict__ hS, const float* __restrict__ wS,
                                       int kbeg, int cp, int bp, ull acc[6])
{
#pragma unroll
    for (int i = 0; i < 6; i++) acc[i] = 0ull;
    const float* hp = hS + 2*bp;
#pragma unroll 4
    for (int kk = 0; kk < 128; kk++) {
        int k = kbeg + kk;
        float2 h = *(const float2*)(hp + k*32);
        ull hx = splat2(h.x), hy = splat2(h.y);
        const ull* w = (const ull*)(wS + k*48 + cp*6);
        ull wr = w[0], wz = w[1], wn = w[2];
        fma2(acc[0], wr, hx); fma2(acc[1], wr, hy);
        fma2(acc[2], wz, hx); fma2(acc[3], wz, hy);
        fma2(acc[4], wn, hx); fma2(acc[5], wn, hy);
    }
}

// cross-half reduction of 6 packed accumulators -> 12 floats (valid for tid<128)
__device__ __forceinline__ void reduce6(ull* red, int half, int lt, const ull a[6], float o[12])
{
    if (half) {
#pragma unroll
        for (int i = 0; i < 6; i++) red[lt*13 + i] = a[i];
    }
    __syncthreads();
    if (!half) {
#pragma unroll
        for (int i = 0; i < 6; i++) {
            float2 m = unp(a[i]), r = unp(red[lt*13 + i]);
            o[i*2 + 0] = m.x + r.x;
            o[i*2 + 1] = m.y + r.y;
        }
    }
}

// ---------------- main persistent kernel ----------------
__global__ __launch_bounds__(256, 1) void gru_main(
    const float* __restrict__ x,
    const float* __restrict__ Wih0, const float* __restrict__ bih0, const float* __restrict__ bhh0,
    const float* __restrict__ bih1, const float* __restrict__ bhh1,
    const float* __restrict__ Wdih, const float* __restrict__ bdih, const float* __restrict__ bdhh,
    const float* __restrict__ Wo, const float* __restrict__ bo,
    float* __restrict__ out)
{
    extern __shared__ float sm[];
    float* sWA  = sm;                      // [256][8][6]   12288
    float* sWB  = sm + 12288;              // [256][8][12]  24576
    float* h0s  = sWB + 24576;             // [256][32]      8192
    float* h1s  = h0s + 8192;              // [256][32]      8192
    ull*   red  = (ull*)(h1s + 8192);      // [128][13]      3328 floats
    float* red2 = ((float*)red) + 3328;    // [32][8]         256
    float* ybuf = red2 + 256;              //                  32

    const int p   = blockIdx.x & 15;
    const int g   = blockIdx.x >> 4;
    const int tid = threadIdx.x;
    const int half = tid >> 7;             // k-half: warps 0-3 -> k[0,128), 4-7 -> k[128,256)
    const int lt  = tid & 127;
    const int cp  = lt >> 4;               // col pair 0..7
    const int bp  = lt & 15;               // batch pair 0..15
    const int kbeg = half << 7;
    const int c0 = p*16 + cp*2;

    // stage weights + zero h tiles
    {
        const float4* a4 = (const float4*)(d_pA + p*12288);
        float4* da = (float4*)sWA;
        for (int i = tid; i < 3072; i += 256) da[i] = a4[i];
        const float4* b4 = (const float4*)(d_pB + p*24576);
        float4* db = (float4*)sWB;
        for (int i = tid; i < 6144; i += 256) db[i] = b4[i];
        float4 z = make_float4(0.f, 0.f, 0.f, 0.f);
        float4* z0 = (float4*)h0s; float4* z1 = (float4*)h1s;
        for (int i = tid; i < 2048; i += 256) { z0[i] = z; z1[i] = z; }
    }

    // per-thread gate constants (used by tid<128)
    float wi0[6], bi0[6], bh0[6], bi1c[6], bh1c[6];
#pragma unroll
    for (int q = 0; q < 6; q++) {
        int gate = q >> 1, cl = q & 1;
        int j = gate*256 + c0 + cl;
        wi0[q] = Wih0[j]; bi0[q] = bih0[j]; bh0[q] = bhh0[j];
        bi1c[q] = bih1[j]; bh1c[q] = bhh1[j];
    }
    __syncthreads();

    unsigned bar = 0;
    int par = 0;

    // ======================= encoder: 512 steps =======================
    for (int t = 0; t < 512; t++) {
        float xv0 = 0.f, xv1 = 0.f;
        if (!half) {
            xv0 = __ldg(&x[(g*32 + 2*bp    )*512 + t]);
            xv1 = __ldg(&x[(g*32 + 2*bp + 1)*512 + t]);
        }

        // ---- layer 0: gh = h0 @ Whh0^T ----
        ull a0[6];
        gemm48(h0s, sWA, kbeg, cp, bp, a0);
        float acc[12];
        reduce6(red, half, lt, a0, acc);

        if (!half) {
#pragma unroll
            for (int bl = 0; bl < 2; bl++) {
                float xv = bl ? xv1 : xv0;
#pragma unroll
                for (int cl = 0; cl < 2; cl++) {
                    float gr = acc[0 + bl*2 + cl] + bh0[cl];
                    float gz = acc[4 + bl*2 + cl] + bh0[2 + cl];
                    float gn = acc[8 + bl*2 + cl] + bh0[4 + cl];
                    float r  = sigf(xv*wi0[cl]     + bi0[cl]     + gr);
                    float zz = sigf(xv*wi0[2 + cl] + bi0[2 + cl] + gz);
                    float n  = tanh_(xv*wi0[4 + cl] + bi0[4 + cl] + r*gn);
                    float hold = h0s[(c0 + cl)*32 + 2*bp + bl];
                    float hv = (1.0f - zz)*n + zz*hold;
                    d_h0g[((par*NG + g)*256 + c0 + cl)*32 + 2*bp + bl] = hv;
                }
            }
        }
        bar++; gbar(g, bar*16);
        {   // refresh h0s <- h0(t+1)
            const float4* src = (const float4*)(d_h0g + (par*NG + g)*8192);
            float4* dst = (float4*)h0s;
            for (int i = tid; i < 2048; i += 256) dst[i] = __ldcg(src + i);
        }
        __syncthreads();

        // ---- layer 1: gi = ys0 @ Wih1^T ; gh = h1 @ Whh1^T ----
        ull aI[6], aH[6];
#pragma unroll
        for (int i = 0; i < 6; i++) { aI[i] = 0ull; aH[i] = 0ull; }
        {
            const float* hp0 = h0s + 2*bp;
            const float* hp1 = h1s + 2*bp;
#pragma unroll 2
            for (int kk = 0; kk < 128; kk++) {
                int k = kbeg + kk;
                float2 u = *(const float2*)(hp0 + k*32);
                float2 v = *(const float2*)(hp1 + k*32);
                ull ux = splat2(u.x), uy = splat2(u.y);
                ull vx = splat2(v.x), vy = splat2(v.y);
                const ulonglong2* w = (const ulonglong2*)(sWB + (k*8 + cp)*12);
                ulonglong2 w0 = w[0], w1 = w[1], w2 = w[2];
                fma2(aI[0], w0.x, ux); fma2(aI[1], w0.x, uy);
                fma2(aH[0], w0.y, vx); fma2(aH[1], w0.y, vy);
                fma2(aI[2], w1.x, ux); fma2(aI[3], w1.x, uy);
                fma2(aH[2], w1.y, vx); fma2(aH[3], w1.y, vy);
                fma2(aI[4], w2.x, ux); fma2(aI[5], w2.x, uy);
                fma2(aH[4], w2.y, vx); fma2(aH[5], w2.y, vy);
            }
        }
        // reduce 12 packed accumulators across halves
        if (half) {
#pragma unroll
            for (int i = 0; i < 6; i++) { red[lt*13 + i] = aI[i]; red[lt*13 + 6 + i] = aH[i]; }
        }
        __syncthreads();
        if (!half) {
            float accI[12], accH[12];
#pragma unroll
            for (int i = 0; i < 6; i++) {
                float2 mI = unp(aI[i]), rI = unp(red[lt*13 + i]);
                float2 mH = unp(aH[i]), rH = unp(red[lt*13 + 6 + i]);
                accI[i*2] = mI.x + rI.x; accI[i*2 + 1] = mI.y + rI.y;
                accH[i*2] = mH.x + rH.x; accH[i*2 + 1] = mH.y + rH.y;
            }
#pragma unroll
            for (int bl = 0; bl < 2; bl++) {
#pragma unroll
                for (int cl = 0; cl < 2; cl++) {
                    float ir = accI[0 + bl*2 + cl] + bi1c[cl];
                    float iz = accI[4 + bl*2 + cl] + bi1c[2 + cl];
                    float in_ = accI[8 + bl*2 + cl] + bi1c[4 + cl];
                    float hr = accH[0 + bl*2 + cl] + bh1c[cl];
                    float hz = accH[4 + bl*2 + cl] + bh1c[2 + cl];
                    float hn = accH[8 + bl*2 + cl] + bh1c[4 + cl];
                    float r  = sigf(ir + hr);
                    float zz = sigf(iz + hz);
                    float n  = tanh_(in_ + r*hn);
                    float hold = h1s[(c0 + cl)*32 + 2*bp + bl];
                    float hv = (1.0f - zz)*n + zz*hold;
                    d_h1g[((par*NG + g)*256 + c0 + cl)*32 + 2*bp + bl] = hv;
                }
            }
        }
        bar++; gbar(g, bar*16);
        {   // refresh h1s <- h1(t+1)
            const float4* src = (const float4*)(d_h1g + (par*NG + g)*8192);
            float4* dst = (float4*)h1s;
            for (int i = tid; i < 2048; i += 256) dst[i] = __ldcg(src + i);
        }
        __syncthreads();
        par ^= 1;
    }

    // ======================= decoder: 96 steps =======================
    {   // overwrite sWA with packed Wd_hh
        const float4* a4 = (const float4*)(d_pD + p*12288);
        float4* da = (float4*)sWA;
        for (int i = tid; i < 3072; i += 256) da[i] = a4[i];
    }
    float wdi[6], bdi[6], bdh[6], wo0, wo1, bov;
#pragma unroll
    for (int q = 0; q < 6; q++) {
        int j = (q >> 1)*256 + c0 + (q & 1);
        wdi[q] = Wdih[j]; bdi[q] = bdih[j]; bdh[q] = bdhh[j];
    }
    wo0 = Wo[c0]; wo1 = Wo[c0 + 1]; bov = bo[0];
    float inp0 = 0.f, inp1 = 0.f;
    __syncthreads();

    for (int t = 0; t < 96; t++) {
        ull a0[6];
        gemm48(h1s, sWA, kbeg, cp, bp, a0);
        float acc[12];
        reduce6(red, half, lt, a0, acc);

        if (!half) {
            float py0 = 0.f, py1 = 0.f;
#pragma unroll
            for (int bl = 0; bl < 2; bl++) {
                float inp = bl ? inp1 : inp0;
                float py = 0.f;
#pragma unroll
                for (int cl = 0; cl < 2; cl++) {
                    float gr = acc[0 + bl*2 + cl] + bdh[cl];
                    float gz = acc[4 + bl*2 + cl] + bdh[2 + cl];
                    float gn = acc[8 + bl*2 + cl] + bdh[4 + cl];
                    float r  = sigf(inp*wdi[cl]     + bdi[cl]     + gr);
                    float zz = sigf(inp*wdi[2 + cl] + bdi[2 + cl] + gz);
                    float n  = tanh_(inp*wdi[4 + cl] + bdi[4 + cl] + r*gn);
                    float hold = h1s[(c0 + cl)*32 + 2*bp + bl];
                    float hv = (1.0f - zz)*n + zz*hold;
                    d_h1g[((par*NG + g)*256 + c0 + cl)*32 + 2*bp + bl] = hv;
                    py += hv * (cl ? wo1 : wo0);
                }
                if (bl) py1 = py; else py0 = py;
            }
            red2[(2*bp + 0)*8 + cp] = py0;
            red2[(2*bp + 1)*8 + cp] = py1;
        }
        __syncthreads();
        if (tid < 32) {   // per-batch partial over this CTA's 16 cols (fixed order)
            float s = 0.f;
#pragma unroll
            for (int j = 0; j < 8; j++) s += red2[tid*8 + j];
            d_partg[((par*NP + p)*NG + g)*32 + tid] = s;
        }
        bar++; gbar(g, bar*16);

        if (tid < 32) {   // every CTA deterministically reduces the 16 partials
            float s = bov;
#pragma unroll
            for (int q = 0; q < 16; q++)
                s += __ldcg(&d_partg[((par*NP + q)*NG + g)*32 + tid]);
            ybuf[tid] = s;
            if (p == 0) out[(g*32 + tid)*96 + t] = s;
        }
        {   // refresh h1s <- h(t+1)
            const float4* src = (const float4*)(d_h1g + (par*NG + g)*8192);
            float4* dst = (float4*)h1s;
            for (int i = tid; i < 2048; i += 256) dst[i] = __ldcg(src + i);
        }
        __syncthreads();
        if (!half) { inp0 = ybuf[2*bp]; inp1 = ybuf[2*bp + 1]; }
        par ^= 1;
    }
}

// ---------------- launch ----------------
extern "C" void kernel_launch(void* const* d_in, const int* in_sizes, int n_in,
                              void* d_out, int out_size)
{
    const float* x    = (const float*)d_in[0];
    const float* Wih0 = (const float*)d_in[1];
    const float* Whh0 = (const float*)d_in[2];
    const float* bih0 = (const float*)d_in[3];
    const float* bhh0 = (const float*)d_in[4];
    const float* Wih1 = (const float*)d_in[5];
    const float* Whh1 = (const float*)d_in[6];
    const float* bih1 = (const float*)d_in[7];
    const float* bhh1 = (const float*)d_in[8];
    const float* Wdih = (const float*)d_in[9];
    const float* Wdhh = (const float*)d_in[10];
    const float* bdih = (const float*)d_in[11];
    const float* bdhh = (const float*)d_in[12];
    const float* Wo   = (const float*)d_in[13];
    const float* bo   = (const float*)d_in[14];
    float* out = (float*)d_out;

    cudaFuncSetAttribute(gru_main, cudaFuncAttributeMaxDynamicSharedMemorySize, SMEM_BYTES);
    prep_kernel<<<384, 256>>>(Whh0, Wih1, Whh1, Wdhh);
    gru_main<<<NBLK, 256, SMEM_BYTES>>>(x, Wih0, bih0, bhh0, bih1, bhh1,
                                        Wdih, bdih, bdhh, Wo, bo, out);
}

// round 11
// speedup vs baseline: 1.2359x; 1.2359x over previous
#include <cuda_runtime.h>

typedef unsigned long long ull;

#define NG 8           // batch groups (32 batches each)
#define NP 16          // column partitions (16 hidden cols each)
#define NBLK (NG*NP)   // 128 CTAs
#define SM_FLOATS (12288+24576+8192+8192+256+32)
#define SMEM_BYTES (SM_FLOATS*4)

// ---------------- static device scratch (no allocation) ----------------
__device__ float d_pA[NP*256*48];      // W_hh0 packed  [p][k][cp][gate*2+cl]
__device__ float d_pB[NP*256*96];      // W_ih1|W_hh1   [p][k][cp][gate*4+s*2+cl]
__device__ float d_pD[NP*256*48];      // Wd_hh packed like A
__device__ float d_xT[512*256];        // x transposed [t][b]
__device__ float d_h0g[2*NG*256*32];   // double-buffered layer0 h [par][g][col][b]
__device__ float d_h1g[2*NG*256*32];   // layer1 / decoder h
__device__ float d_partg[2*NP*NG*32];  // decoder partial y
__device__ unsigned int d_cnt[NG];     // group barrier counters

// ---------------- prep: reset barriers, pack weights, transpose x ----------------
__global__ void prep_kernel(const float* __restrict__ Whh0, const float* __restrict__ Wih1,
                            const float* __restrict__ Whh1, const float* __restrict__ Wdhh,
                            const float* __restrict__ x)
{
    int idx = blockIdx.x*blockDim.x + threadIdx.x;
    int stride = gridDim.x*blockDim.x;
    if (idx < NG) d_cnt[idx] = 0u;
    for (int i = idx; i < NP*256*48; i += stride) {
        int q = i % 6, cp = (i/6) & 7, k = (i/48) & 255, p = i/12288;
        int gate = q >> 1, cl = q & 1;
        int col = p*16 + cp*2 + cl;
        int src = (gate*256 + col)*256 + k;
        d_pA[i] = Whh0[src];
        d_pD[i] = Wdhh[src];
    }
    for (int i = idx; i < NP*256*96; i += stride) {
        int q = i % 12, cp = (i/12) & 7, k = (i/96) & 255, p = i/24576;
        int gate = q >> 2, s = (q >> 1) & 1, cl = q & 1;
        int col = p*16 + cp*2 + cl;
        int src = (gate*256 + col)*256 + k;
        d_pB[i] = s ? Whh1[src] : Wih1[src];
    }
    for (int i = idx; i < 512*256; i += stride)
        d_xT[i] = x[(i & 255)*512 + (i >> 8)];
    for (int i = idx; i < 2*NG*256*32; i += stride)
        d_h1g[i] = 0.0f;   // phase-0 refresh of h1 must read zeros
}

// ---------------- helpers ----------------
__device__ __forceinline__ ull splat2(float v){ ull r; asm("mov.b64 %0, {%1,%1};" : "=l"(r) : "f"(v)); return r; }
__device__ __forceinline__ void fma2(ull &d, ull a, ull b){ asm("fma.rn.f32x2 %0, %1, %2, %0;" : "+l"(d) : "l"(a), "l"(b)); }
__device__ __forceinline__ float2 unp(ull v){ float2 f; asm("mov.b64 {%0,%1}, %2;" : "=f"(f.x), "=f"(f.y) : "l"(v)); return f; }
__device__ __forceinline__ float sigf(float v){ return 1.0f/(1.0f + __expf(-v)); }
__device__ __forceinline__ float tanh_(float v){
    float a = fabsf(v), e = __expf(-2.0f*a);
    float t = (1.0f - e)/(1.0f + e);
    return v < 0.0f ? -t : t;
}
// cross-k-half reduce: low half + high half (fixed order for both lanes groups;
// only kh==0 lanes' results are ever stored, and they compute low+high like R9)
__device__ __forceinline__ ull shred(ull v){
    ull o = __shfl_xor_sync(0xffffffffu, v, 16);
    ull r; asm("add.rn.f32x2 %0, %1, %2;" : "=l"(r) : "l"(v), "l"(o));
    return r;
}

// per-group barrier: release(prior stores) -> arrive -> spin -> acquire
__device__ __forceinline__ void gbar(int g, unsigned target){
    __threadfence();
    __syncthreads();
    if (threadIdx.x == 0) {
        atomicAdd(&d_cnt[g], 1u);
        while (*(volatile unsigned*)&d_cnt[g] < target) __nanosleep(16);
        __threadfence();
    }
    __syncthreads();
}

// ---------------- main persistent kernel ----------------
__global__ __launch_bounds__(256, 1) void gru_main(
    const float* __restrict__ Wih0, const float* __restrict__ bih0, const float* __restrict__ bhh0,
    const float* __restrict__ bih1, const float* __restrict__ bhh1,
    const float* __restrict__ Wdih, const float* __restrict__ bdih, const float* __restrict__ bdhh,
    const float* __restrict__ Wo, const float* __restrict__ bo,
    float* __restrict__ out)
{
    extern __shared__ float sm[];
    float* sWA  = sm;                      // [256][8][6]   12288
    float* sWB  = sm + 12288;              // [256][8][12]  24576
    float* h0s  = sWB + 24576;             // [256][32]      8192
    float* h1s  = h0s + 8192;              // [256][32]      8192
    float* red2 = h1s + 8192;              // [32][8]         256
    float* ybuf = red2 + 256;              //                  32

    const int p    = blockIdx.x & 15;
    const int g    = blockIdx.x >> 4;
    const int tid  = threadIdx.x;
    const int cp   = tid >> 5;             // warp id = col pair 0..7
    const int lane = tid & 31;
    const int kh   = lane >> 4;            // k half within warp
    const int bp   = lane & 15;            // batch pair 0..15
    const int kbeg = kh << 7;
    const int c0   = p*16 + cp*2;

    // stage weights + zero h tiles
    {
        const float4* a4 = (const float4*)(d_pA + p*12288);
        float4* da = (float4*)sWA;
        for (int i = tid; i < 3072; i += 256) da[i] = a4[i];
        const float4* b4 = (const float4*)(d_pB + p*24576);
        float4* db = (float4*)sWB;
        for (int i = tid; i < 6144; i += 256) db[i] = b4[i];
        float4 z = make_float4(0.f, 0.f, 0.f, 0.f);
        float4* z0 = (float4*)h0s; float4* z1 = (float4*)h1s;
        for (int i = tid; i < 2048; i += 256) { z0[i] = z; z1[i] = z; }
    }

    // per-thread gate constants
    float wi0[6], bi0[6], bh0[6], bi1c[6], bh1c[6];
#pragma unroll
    for (int q = 0; q < 6; q++) {
        int gate = q >> 1, cl = q & 1;
        int j = gate*256 + c0 + cl;
        wi0[q] = Wih0[j]; bi0[q] = bih0[j]; bh0[q] = bhh0[j];
        bi1c[q] = bih1[j]; bh1c[q] = bhh1[j];
    }
    __syncthreads();

    unsigned bar = 0;
    int par = 0;

    // ============ encoder: 512 merged phases (layer0 t=u, layer1 t=u-1) ============
    for (int u = 0; u < 512; u++) {
        float2 xv2 = *(const float2*)(d_xT + u*256 + g*32 + 2*bp);

        ull aA[6], aI[6], aH[6];
#pragma unroll
        for (int i = 0; i < 6; i++) { aA[i] = 0ull; aI[i] = 0ull; aH[i] = 0ull; }
        {
            const float* h0p = h0s + 2*bp + kbeg*32;
            const float* h1p = h1s + 2*bp + kbeg*32;
            const float* wap = sWA + cp*6  + kbeg*48;
            const float* wbp = sWB + cp*12 + kbeg*96;
#pragma unroll 2
            for (int kk = 0; kk < 128; kk++) {
                float2 uu = *(const float2*)h0p;
                float2 vv = *(const float2*)h1p;
                ull ux = splat2(uu.x), uy = splat2(uu.y);
                ull vx = splat2(vv.x), vy = splat2(vv.y);
                const ull* wa = (const ull*)wap;
                ull a0 = wa[0], a1 = wa[1], a2 = wa[2];
                const ulonglong2* wb = (const ulonglong2*)wbp;
                ulonglong2 w0 = wb[0], w1 = wb[1], w2 = wb[2];
                fma2(aA[0], a0, ux);   fma2(aA[1], a0, uy);
                fma2(aA[2], a1, ux);   fma2(aA[3], a1, uy);
                fma2(aA[4], a2, ux);   fma2(aA[5], a2, uy);
                fma2(aI[0], w0.x, ux); fma2(aI[1], w0.x, uy);
                fma2(aH[0], w0.y, vx); fma2(aH[1], w0.y, vy);
                fma2(aI[2], w1.x, ux); fma2(aI[3], w1.x, uy);
                fma2(aH[2], w1.y, vx); fma2(aH[3], w1.y, vy);
                fma2(aI[4], w2.x, ux); fma2(aI[5], w2.x, uy);
                fma2(aH[4], w2.y, vx); fma2(aH[5], w2.y, vy);
                h0p += 32; h1p += 32; wap += 48; wbp += 96;
            }
        }
        // shfl-reduce across k halves
        float accA[12], accI[12], accH[12];
#pragma unroll
        for (int i = 0; i < 6; i++) {
            float2 fa = unp(shred(aA[i]));
            float2 fi = unp(shred(aI[i]));
            float2 fh = unp(shred(aH[i]));
            accA[i*2] = fa.x; accA[i*2+1] = fa.y;
            accI[i*2] = fi.x; accI[i*2+1] = fi.y;
            accH[i*2] = fh.x; accH[i*2+1] = fh.y;
        }

        // ---- layer0 epilogue: h0(u+1) ----
        {
            float hv[2][2];
#pragma unroll
            for (int bl = 0; bl < 2; bl++) {
                float xv = bl ? xv2.y : xv2.x;
#pragma unroll
                for (int cl = 0; cl < 2; cl++) {
                    float gr = accA[0 + bl*2 + cl] + bh0[cl];
                    float gz = accA[4 + bl*2 + cl] + bh0[2 + cl];
                    float gn = accA[8 + bl*2 + cl] + bh0[4 + cl];
                    float r  = sigf(xv*wi0[cl]     + bi0[cl]     + gr);
                    float zz = sigf(xv*wi0[2 + cl] + bi0[2 + cl] + gz);
                    float n  = tanh_(xv*wi0[4 + cl] + bi0[4 + cl] + r*gn);
                    float hold = h0s[(c0 + cl)*32 + 2*bp + bl];
                    hv[bl][cl] = (1.0f - zz)*n + zz*hold;
                }
            }
            if (kh == 0) {
                float* dst = d_h0g + ((par*NG + g)*256 + c0)*32 + 2*bp;
                *(float2*)(dst)      = make_float2(hv[0][0], hv[1][0]);
                *(float2*)(dst + 32) = make_float2(hv[0][1], hv[1][1]);
            }
        }
        // ---- layer1 epilogue: h1(u) (skip at u==0) ----
        if (u != 0) {
            float hv[2][2];
#pragma unroll
            for (int bl = 0; bl < 2; bl++) {
#pragma unroll
                for (int cl = 0; cl < 2; cl++) {
                    float ir  = accI[0 + bl*2 + cl] + bi1c[cl];
                    float iz  = accI[4 + bl*2 + cl] + bi1c[2 + cl];
                    float in_ = accI[8 + bl*2 + cl] + bi1c[4 + cl];
                    float hr  = accH[0 + bl*2 + cl] + bh1c[cl];
                    float hz  = accH[4 + bl*2 + cl] + bh1c[2 + cl];
                    float hn  = accH[8 + bl*2 + cl] + bh1c[4 + cl];
                    float r  = sigf(ir + hr);
                    float zz = sigf(iz + hz);
                    float n  = tanh_(in_ + r*hn);
                    float hold = h1s[(c0 + cl)*32 + 2*bp + bl];
                    hv[bl][cl] = (1.0f - zz)*n + zz*hold;
                }
            }
            if (kh == 0) {
                float* dst = d_h1g + ((par*NG + g)*256 + c0)*32 + 2*bp;
                *(float2*)(dst)      = make_float2(hv[0][0], hv[1][0]);
                *(float2*)(dst + 32) = make_float2(hv[0][1], hv[1][1]);
            }
        }

        bar++; gbar(g, bar*16);
        {   // refresh both h tiles
            const float4* s0 = (const float4*)(d_h0g + (par*NG + g)*8192);
            const float4* s1 = (const float4*)(d_h1g + (par*NG + g)*8192);
            float4* dd0 = (float4*)h0s; float4* dd1 = (float4*)h1s;
            for (int i = tid; i < 2048; i += 256) { dd0[i] = __ldcg(s0 + i); dd1[i] = __ldcg(s1 + i); }
        }
        __syncthreads();
        par ^= 1;
    }

    // ============ drain: layer1 step 511 -> h1(512) ============
    {
        ull aI[6], aH[6];
#pragma unroll
        for (int i = 0; i < 6; i++) { aI[i] = 0ull; aH[i] = 0ull; }
        const float* h0p = h0s + 2*bp + kbeg*32;
        const float* h1p = h1s + 2*bp + kbeg*32;
        const float* wbp = sWB + cp*12 + kbeg*96;
#pragma unroll 2
        for (int kk = 0; kk < 128; kk++) {
            float2 uu = *(const float2*)h0p;
            float2 vv = *(const float2*)h1p;
            ull ux = splat2(uu.x), uy = splat2(uu.y);
            ull vx = splat2(vv.x), vy = splat2(vv.y);
            const ulonglong2* wb = (const ulonglong2*)wbp;
            ulonglong2 w0 = wb[0], w1 = wb[1], w2 = wb[2];
            fma2(aI[0], w0.x, ux); fma2(aI[1], w0.x, uy);
            fma2(aH[0], w0.y, vx); fma2(aH[1], w0.y, vy);
            fma2(aI[2], w1.x, ux); fma2(aI[3], w1.x, uy);
            fma2(aH[2], w1.y, vx); fma2(aH[3], w1.y, vy);
            fma2(aI[4], w2.x, ux); fma2(aI[5], w2.x, uy);
            fma2(aH[4], w2.y, vx); fma2(aH[5], w2.y, vy);
            h0p += 32; h1p += 32; wbp += 96;
        }
        float accI[12], accH[12];
#pragma unroll
        for (int i = 0; i < 6; i++) {
            float2 fi = unp(shred(aI[i]));
            float2 fh = unp(shred(aH[i]));
            accI[i*2] = fi.x; accI[i*2+1] = fi.y;
            accH[i*2] = fh.x; accH[i*2+1] = fh.y;
        }
        float hv[2][2];
#pragma unroll
        for (int bl = 0; bl < 2; bl++) {
#pragma unroll
            for (int cl = 0; cl < 2; cl++) {
                float ir  = accI[0 + bl*2 + cl] + bi1c[cl];
                float iz  = accI[4 + bl*2 + cl] + bi1c[2 + cl];
                float in_ = accI[8 + bl*2 + cl] + bi1c[4 + cl];
                float hr  = accH[0 + bl*2 + cl] + bh1c[cl];
                float hz  = accH[4 + bl*2 + cl] + bh1c[2 + cl];
                float hn  = accH[8 + bl*2 + cl] + bh1c[4 + cl];
                float r  = sigf(ir + hr);
                float zz = sigf(iz + hz);
                float n  = tanh_(in_ + r*hn);
                float hold = h1s[(c0 + cl)*32 + 2*bp + bl];
                hv[bl][cl] = (1.0f - zz)*n + zz*hold;
            }
        }
        if (kh == 0) {
            float* dst = d_h1g + ((par*NG + g)*256 + c0)*32 + 2*bp;
            *(float2*)(dst)      = make_float2(hv[0][0], hv[1][0]);
            *(float2*)(dst + 32) = make_float2(hv[0][1], hv[1][1]);
        }
        bar++; gbar(g, bar*16);
        const float4* s1 = (const float4*)(d_h1g + (par*NG + g)*8192);
        float4* dd1 = (float4*)h1s;
        for (int i = tid; i < 2048; i += 256) dd1[i] = __ldcg(s1 + i);
        __syncthreads();
        par ^= 1;
    }

    // ============ decoder: 96 steps ============
    {   // overwrite sWA with packed Wd_hh
        const float4* a4 = (const float4*)(d_pD + p*12288);
        float4* da = (float4*)sWA;
        for (int i = tid; i < 3072; i += 256) da[i] = a4[i];
    }
    float wdi[6], bdi[6], bdh[6], wo0, wo1, bov;
#pragma unroll
    for (int q = 0; q < 6; q++) {
        int j = (q >> 1)*256 + c0 + (q & 1);
        wdi[q] = Wdih[j]; bdi[q] = bdih[j]; bdh[q] = bdhh[j];
    }
    wo0 = Wo[c0]; wo1 = Wo[c0 + 1]; bov = bo[0];
    float inp0 = 0.f, inp1 = 0.f;
    __syncthreads();

    for (int t = 0; t < 96; t++) {
        ull aD[6];
#pragma unroll
        for (int i = 0; i < 6; i++) aD[i] = 0ull;
        {
            const float* h1p = h1s + 2*bp + kbeg*32;
            const float* wap = sWA + cp*6 + kbeg*48;
#pragma unroll 4
            for (int kk = 0; kk < 128; kk++) {
                float2 vv = *(const float2*)h1p;
                ull vx = splat2(vv.x), vy = splat2(vv.y);
                const ull* wa = (const ull*)wap;
                ull a0 = wa[0], a1 = wa[1], a2 = wa[2];
                fma2(aD[0], a0, vx); fma2(aD[1], a0, vy);
                fma2(aD[2], a1, vx); fma2(aD[3], a1, vy);
                fma2(aD[4], a2, vx); fma2(aD[5], a2, vy);
                h1p += 32; wap += 48;
            }
        }
        float acc[12];
#pragma unroll
        for (int i = 0; i < 6; i++) {
            float2 f = unp(shred(aD[i]));
            acc[i*2] = f.x; acc[i*2+1] = f.y;
        }

        float py0 = 0.f, py1 = 0.f;
        float hv[2][2];
#pragma unroll
        for (int bl = 0; bl < 2; bl++) {
            float inp = bl ? inp1 : inp0;
            float py = 0.f;
#pragma unroll
            for (int cl = 0; cl < 2; cl++) {
                float gr = acc[0 + bl*2 + cl] + bdh[cl];
                float gz = acc[4 + bl*2 + cl] + bdh[2 + cl];
                float gn = acc[8 + bl*2 + cl] + bdh[4 + cl];
                float r  = sigf(inp*wdi[cl]     + bdi[cl]     + gr);
                float zz = sigf(inp*wdi[2 + cl] + bdi[2 + cl] + gz);
                float n  = tanh_(inp*wdi[4 + cl] + bdi[4 + cl] + r*gn);
                float hold = h1s[(c0 + cl)*32 + 2*bp + bl];
                hv[bl][cl] = (1.0f - zz)*n + zz*hold;
                py += hv[bl][cl] * (cl ? wo1 : wo0);
            }
            if (bl) py1 = py; else py0 = py;
        }
        if (kh == 0) {
            float* dst = d_h1g + ((par*NG + g)*256 + c0)*32 + 2*bp;
            *(float2*)(dst)      = make_float2(hv[0][0], hv[1][0]);
            *(float2*)(dst + 32) = make_float2(hv[0][1], hv[1][1]);
            red2[(2*bp + 0)*8 + cp] = py0;
            red2[(2*bp + 1)*8 + cp] = py1;
        }
        __syncthreads();
        if (tid < 32) {   // per-batch partial over this CTA's 16 cols (fixed order)
            float s = 0.f;
#pragma unroll
            for (int j = 0; j < 8; j++) s += red2[tid*8 + j];
            d_partg[((par*NP + p)*NG + g)*32 + tid] = s;
        }
        bar++; gbar(g, bar*16);

        if (tid < 32) {   // every CTA deterministically reduces the 16 partials
            float s = bov;
#pragma unroll
            for (int q = 0; q < 16; q++)
                s += __ldcg(&d_partg[((par*NP + q)*NG + g)*32 + tid]);
            ybuf[tid] = s;
            if (p == 0) out[(g*32 + tid)*96 + t] = s;
        }
        {   // refresh h1s <- h(t+1)
            const float4* src = (const float4*)(d_h1g + (par*NG + g)*8192);
            float4* dst = (float4*)h1s;
            for (int i = tid; i < 2048; i += 256) dst[i] = __ldcg(src + i);
        }
        __syncthreads();
        inp0 = ybuf[2*bp]; inp1 = ybuf[2*bp + 1];
        par ^= 1;
    }
}

// ---------------- launch ----------------
extern "C" void kernel_launch(void* const* d_in, const int* in_sizes, int n_in,
                              void* d_out, int out_size)
{
    const float* x    = (const float*)d_in[0];
    const float* Wih0 = (const float*)d_in[1];
    const float* Whh0 = (const float*)d_in[2];
    const float* bih0 = (const float*)d_in[3];
    const float* bhh0 = (const float*)d_in[4];
    const float* Wih1 = (const float*)d_in[5];
    const float* Whh1 = (const float*)d_in[6];
    const float* bih1 = (const float*)d_in[7];
    const float* bhh1 = (const float*)d_in[8];
    const float* Wdih = (const float*)d_in[9];
    const float* Wdhh = (const float*)d_in[10];
    const float* bdih = (const float*)d_in[11];
    const float* bdhh = (const float*)d_in[12];
    const float* Wo   = (const float*)d_in[13];
    const float* bo   = (const float*)d_in[14];
    float* out = (float*)d_out;

    cudaFuncSetAttribute(gru_main, cudaFuncAttributeMaxDynamicSharedMemorySize, SMEM_BYTES);
    prep_kernel<<<384, 256>>>(Whh0, Wih1, Whh1, Wdhh, x);
    gru_main<<<NBLK, 256, SMEM_BYTES>>>(Wih0, bih0, bhh0, bih1, bhh1,
                                        Wdih, bdih, bdhh, Wo, bo, out);
}